// round 3
// baseline (speedup 1.0000x reference)
#include <cuda_runtime.h>
#include <cfloat>
#include <cstdint>

// Problem: V [1024, 8192] fp32 -> out [1024, 8192] fp32
#define Mm    8192
#define Nn    1024
#define STEPS 8192          // 8 rounds * 1024 rows
#define C     8             // cluster size: one cluster covers all columns
#define TPB   1024          // 8 CTAs x 1024 threads = 8192 columns
#define LOG2E 1.4426950408889634f

__device__ float g_rmin[Nn];

// ---------------------------------------------------------------------------
// init: per-row min of V.
// ---------------------------------------------------------------------------
__global__ void softrr_init(const float* __restrict__ V) {
    const int b = blockIdx.x, t = threadIdx.x;
    const float* row = V + (size_t)b * Mm;
    float mn = FLT_MAX;
    for (int j = t; j < Mm; j += 256) mn = fminf(mn, row[j]);
    #pragma unroll
    for (int o = 16; o; o >>= 1) mn = fminf(mn, __shfl_down_sync(0xffffffffu, mn, o));
    __shared__ float s[8];
    if ((t & 31) == 0) s[t >> 5] = mn;
    __syncthreads();
    if (t == 0) {
        float r = s[0];
        #pragma unroll
        for (int w = 1; w < 8; w++) r = fminf(r, s[w]);
        g_rmin[b] = r;
    }
}

// ------------------------- smem/DSMEM primitives ---------------------------
__device__ __forceinline__ float ld_vol_f32(uint32_t a) {
    float v; asm volatile("ld.volatile.shared.f32 %0, [%1];" : "=f"(v) : "r"(a));
    return v;
}
__device__ __forceinline__ void ld_vol_v4(uint32_t a, float4& f) {
    asm volatile("ld.volatile.shared.v4.f32 {%0,%1,%2,%3}, [%4];"
                 : "=f"(f.x), "=f"(f.y), "=f"(f.z), "=f"(f.w) : "r"(a));
}
__device__ __forceinline__ void st_vol_f32(uint32_t a, float v) {
    asm volatile("st.volatile.shared.f32 [%0], %1;" :: "r"(a), "f"(v) : "memory");
}
__device__ __forceinline__ void st_remote(uint32_t local_addr, int rank, float v) {
    uint32_t ra;
    asm volatile("mapa.shared::cluster.u32 %0, %1, %2;" : "=r"(ra) : "r"(local_addr), "r"(rank));
    asm volatile("st.shared::cluster.f32 [%0], %1;" :: "r"(ra), "f"(v) : "memory");
}
__device__ __forceinline__ float ex2(float z) {
    float e; asm("ex2.approx.f32 %0, %1;" : "=f"(e) : "f"(z));
    return e;
}
__device__ __forceinline__ float bfly_sum(float p) {
    #pragma unroll
    for (int o = 16; o; o >>= 1) p += __shfl_xor_sync(0xffffffffu, p, o);
    return p;
}

// ---------------------------------------------------------------------------
// main: ONE cluster, 8 CTAs x 1024 threads, barrier-free softmax scan.
// Per step r (parity sign s = ((r>>1)&1) ? - : +, slot ring depth 2):
//   every warp:  e=2^(a2*c); p=warpsum(e); lanes 0-7 push  s*p  to
//                slot[r&1][rank*32+wid] of ALL 8 CTAs (DSMEM).
//   warp 0:      polls its LOCAL 256 slots for the expected sign, reduces in
//                fixed order -> S (bit-identical in every CTA), publishes
//                s*S to s_S[r&1].
//   warps 1-31:  spin on the single broadcast word s_S[r&1].
//   all:         y=e/S; out[row]+=y; c=fma(-y,c,c).
// Stale values always carry the opposite sign -> no zeroing, no barriers.
// ---------------------------------------------------------------------------
__global__ void __launch_bounds__(TPB, 1) __cluster_dims__(C, 1, 1)
softrr_main(const float* __restrict__ V, float* __restrict__ out) {
    __shared__ float s_rmin[Nn];
    __shared__ __align__(16) float s_slot[2 * 256];   // [phase][publisher 0..255]
    __shared__ float s_S[2];

    const int tid  = threadIdx.x;
    const int lane = tid & 31;
    const int wid  = tid >> 5;
    const int rank = blockIdx.x;
    const int col  = rank * TPB + tid;

    const uint32_t slot_base = (uint32_t)__cvta_generic_to_shared(s_slot);
    const uint32_t sS_base   = (uint32_t)__cvta_generic_to_shared(s_S);

    if (tid < 512) s_slot[tid] = 0.0f;
    if (tid < 2)   s_S[tid]    = 0.0f;
    s_rmin[tid] = g_rmin[tid];
    __syncthreads();
    asm volatile("barrier.cluster.arrive.aligned;" ::: "memory");
    asm volatile("barrier.cluster.wait.aligned;"   ::: "memory");

    float c     = 1.0f;
    float a2    = (V[col] - s_rmin[0] + 1.0f) * LOG2E;  // row 0
    float o_acc = 0.0f;                                 // round 0 overwrites
    float a2_next = 0.0f, o_next = 0.0f;

    const uint32_t my_slot_off = (uint32_t)((rank << 5) + wid) * 4u;

    for (int r = 0; r < STEPS; r++) {
        const int  ph  = r & 1;
        const bool neg = (r >> 1) & 1;

        // --- compute + publish (critical path resumes from prior step's S)
        const float e = ex2(a2 * c);
        const float p = bfly_sum(e);                 // all lanes hold warp sum
        if (lane < C)
            st_remote(slot_base + (uint32_t)(ph << 10) + my_slot_off, lane,
                      neg ? -p : p);

        // --- latency slack: prefetch next row's V / out, fold constants
        if (r + 1 < STEPS) {
            const int rn = (r + 1) & (Nn - 1);
            const float v = V[(size_t)rn * Mm + col];
            a2_next = (v - s_rmin[rn] + 1.0f) * LOG2E;
            o_next  = (r + 1 >= Nn) ? out[(size_t)rn * Mm + col] : 0.0f;
        }

        // --- obtain S
        float S;
        if (wid == 0) {
            const uint32_t a0 = slot_base + (uint32_t)(ph << 10) + (uint32_t)lane * 32u;
            float4 A, B;
            bool ok;
            do {
                ld_vol_v4(a0,      A);
                ld_vol_v4(a0 + 16, B);
                if (neg) ok = (A.x < 0.f) & (A.y < 0.f) & (A.z < 0.f) & (A.w < 0.f) &
                              (B.x < 0.f) & (B.y < 0.f) & (B.z < 0.f) & (B.w < 0.f);
                else     ok = (A.x > 0.f) & (A.y > 0.f) & (A.z > 0.f) & (A.w > 0.f) &
                              (B.x > 0.f) & (B.y > 0.f) & (B.z > 0.f) & (B.w > 0.f);
            } while (__ballot_sync(0xffffffffu, ok) != 0xffffffffu);
            // fixed-order reduce (identical everywhere -> bit-identical S)
            float t = ((fabsf(A.x) + fabsf(A.y)) + (fabsf(A.z) + fabsf(A.w)))
                    + ((fabsf(B.x) + fabsf(B.y)) + (fabsf(B.z) + fabsf(B.w)));
            S = bfly_sum(t);
            if (lane == 0) st_vol_f32(sS_base + (uint32_t)ph * 4u, neg ? -S : S);
        } else {
            const uint32_t sa = sS_base + (uint32_t)ph * 4u;
            float sv;
            if (neg) { do { sv = ld_vol_f32(sa); } while (!(sv < 0.0f)); }
            else     { do { sv = ld_vol_f32(sa); } while (!(sv > 0.0f)); }
            S = fabsf(sv);
        }

        // --- epilogue: y, out accumulate, c update
        const float y = __fdividef(e, S);
        out[(size_t)(r & (Nn - 1)) * Mm + col] = o_acc + y;
        c = __fmaf_rn(-y, c, c);

        a2    = a2_next;
        o_acc = o_next;
    }
}

extern "C" void kernel_launch(void* const* d_in, const int* in_sizes, int n_in,
                              void* d_out, int out_size) {
    const float* V = (const float*)d_in[0];
    float* out = (float*)d_out;
    (void)in_sizes; (void)n_in; (void)out_size;

    softrr_init<<<Nn, 256>>>(V);
    softrr_main<<<C, TPB>>>(V, out);
}

// round 4
// speedup vs baseline: 1.4135x; 1.4135x over previous
#include <cuda_runtime.h>
#include <cfloat>
#include <cstdint>

// Problem: V [1024, 8192] fp32 -> out [1024, 8192] fp32
#define Mm    8192
#define Nn    1024
#define STEPS 8192          // 8 rounds * 1024 rows
#define C     8             // cluster CTAs
#define TPB   256           // 8 warps per CTA
#define K     4             // columns per thread  (C*TPB*K == Mm)
#define LOG2E 1.4426950408889634f

__device__ float g_rmin[Nn];

// ---------------------------------------------------------------------------
__global__ void softrr_init(const float* __restrict__ V) {
    const int b = blockIdx.x, t = threadIdx.x;
    const float* row = V + (size_t)b * Mm;
    float mn = FLT_MAX;
    for (int j = t; j < Mm; j += 256) mn = fminf(mn, row[j]);
    #pragma unroll
    for (int o = 16; o; o >>= 1) mn = fminf(mn, __shfl_down_sync(0xffffffffu, mn, o));
    __shared__ float s[8];
    if ((t & 31) == 0) s[t >> 5] = mn;
    __syncthreads();
    if (t == 0) {
        float r = s[0];
        #pragma unroll
        for (int w = 1; w < 8; w++) r = fminf(r, s[w]);
        g_rmin[b] = r;
    }
}

// ------------------------- primitives --------------------------------------
__device__ __forceinline__ float ld_vol_f32(uint32_t a) {
    float v; asm volatile("ld.volatile.shared.f32 %0, [%1];" : "=f"(v) : "r"(a));
    return v;
}
__device__ __forceinline__ void ld_vol_v4(uint32_t a, float4& f) {
    asm volatile("ld.volatile.shared.v4.f32 {%0,%1,%2,%3}, [%4];"
                 : "=f"(f.x), "=f"(f.y), "=f"(f.z), "=f"(f.w) : "r"(a));
}
__device__ __forceinline__ void st_vol_f32(uint32_t a, float v) {
    asm volatile("st.volatile.shared.f32 [%0], %1;" :: "r"(a), "f"(v) : "memory");
}
__device__ __forceinline__ void st_remote(uint32_t local_addr, int rank, float v) {
    uint32_t ra;
    asm volatile("mapa.shared::cluster.u32 %0, %1, %2;" : "=r"(ra) : "r"(local_addr), "r"(rank));
    asm volatile("st.shared::cluster.f32 [%0], %1;" :: "r"(ra), "f"(v) : "memory");
}
__device__ __forceinline__ float ex2(float z) {
    float e; asm("ex2.approx.f32 %0, %1;" : "=f"(e) : "f"(z));
    return e;
}
__device__ __forceinline__ float rcp(float x) {
    float r; asm("rcp.approx.f32 %0, %1;" : "=f"(r) : "f"(x));
    return r;
}

// ---------------------------------------------------------------------------
// ONE cluster: 8 CTAs x 256 threads x 4 columns/thread. Barrier-free scan.
// Step r: phase ph=r&1, expected sign s = ((r>>1)&1) ? - : +.
//   each warp:  e_k = 2^(a2_k*c_k); esum = fixed sum of 4; p = bfly32(esum);
//               lane0 STS ±p -> s_wp[ph][wid]           (8 warps/CTA)
//   warp 0:     polls 8 local s_wp words (sign flags), 3-level xor-combine,
//               lanes 0-7 push ±P into slot[ph][myrank] of ALL 8 CTAs (DSMEM)
//   all warps:  poll LOCAL slot[ph][0..8) via 2x broadcast ld.volatile.v4,
//               S = fixed serial sum of 8 |.| -> bit-identical everywhere
//   epilogue:   rinv=rcp(S); y_k=e_k*rinv; out += y_k; c_k = fma(-y_k,c_k,c_k)
// Stale ring values carry the opposite sign -> no zeroing, no barriers.
// ---------------------------------------------------------------------------
__global__ void __launch_bounds__(TPB, 1) __cluster_dims__(C, 1, 1)
softrr_main(const float* __restrict__ V, float* __restrict__ out) {
    __shared__ float s_rmin[Nn];
    __shared__ __align__(16) float s_wp[2 * 8];     // [phase][warp]
    __shared__ __align__(16) float s_slot[2 * 8];   // [phase][rank]

    const int tid  = threadIdx.x;
    const int lane = tid & 31;
    const int wid  = tid >> 5;
    const int rank = blockIdx.x;
    const int col0 = rank * (TPB * K) + tid;        // 4 cols: col0 + k*TPB

    const uint32_t wp_base   = (uint32_t)__cvta_generic_to_shared(s_wp);
    const uint32_t slot_base = (uint32_t)__cvta_generic_to_shared(s_slot);

    if (tid < 16) { s_wp[tid] = 0.0f; s_slot[tid] = 0.0f; }
    #pragma unroll
    for (int i = 0; i < Nn / TPB; i++) s_rmin[i * TPB + tid] = g_rmin[i * TPB + tid];
    __syncthreads();
    asm volatile("barrier.cluster.arrive.aligned;" ::: "memory");
    asm volatile("barrier.cluster.wait.aligned;"   ::: "memory");

    float c[K], a2[K], o_acc[K], a2n[K], o_nx[K];
    #pragma unroll
    for (int k = 0; k < K; k++) {
        c[k]     = 1.0f;
        a2[k]    = (V[col0 + k * TPB] - s_rmin[0] + 1.0f) * LOG2E;  // row 0
        o_acc[k] = 0.0f;                                            // round 0 overwrites
    }

    for (int r = 0; r < STEPS; r++) {
        const int  ph  = r & 1;
        const bool neg = (r >> 1) & 1;

        // --- compute e's and warp partial
        float e[K];
        #pragma unroll
        for (int k = 0; k < K; k++) e[k] = ex2(a2[k] * c[k]);
        float esum = (e[0] + e[1]) + (e[2] + e[3]);
        #pragma unroll
        for (int o = 16; o; o >>= 1) esum += __shfl_xor_sync(0xffffffffu, esum, o);
        if (lane == 0)
            st_vol_f32(wp_base + (uint32_t)(ph * 8 + wid) * 4u, neg ? -esum : esum);

        // --- warp0: gather 8 warp partials, combine, DSMEM-publish to all CTAs
        if (wid == 0) {
            const uint32_t wa = wp_base + (uint32_t)(ph * 8 + (lane & 7)) * 4u;
            float w; bool ok;
            do {
                w  = ld_vol_f32(wa);
                ok = neg ? (w < 0.0f) : (w > 0.0f);
            } while (__ballot_sync(0xffffffffu, ok) != 0xffffffffu);
            float P = fabsf(w);
            #pragma unroll
            for (int o = 4; o; o >>= 1) P += __shfl_xor_sync(0xffffffffu, P, o);
            if (lane < C)
                st_remote(slot_base + (uint32_t)(ph * 8 + rank) * 4u, lane,
                          neg ? -P : P);
        }

        // --- latency slack: prefetch next row's V / out elements
        if (r + 1 < STEPS) {
            const int rn = (r + 1) & (Nn - 1);
            const float rm = s_rmin[rn];
            #pragma unroll
            for (int k = 0; k < K; k++) {
                a2n[k] = (V[(size_t)rn * Mm + col0 + k * TPB] - rm + 1.0f) * LOG2E;
                o_nx[k] = (r + 1 >= Nn) ? out[(size_t)rn * Mm + col0 + k * TPB] : 0.0f;
            }
        }

        // --- all warps: poll local 8 slots (broadcast v4 loads), fixed-order sum
        const uint32_t sa = slot_base + (uint32_t)(ph * 8) * 4u;
        float4 A, B; bool ok;
        do {
            ld_vol_v4(sa, A);
            ld_vol_v4(sa + 16, B);
            if (neg) ok = (A.x < 0.f) & (A.y < 0.f) & (A.z < 0.f) & (A.w < 0.f) &
                          (B.x < 0.f) & (B.y < 0.f) & (B.z < 0.f) & (B.w < 0.f);
            else     ok = (A.x > 0.f) & (A.y > 0.f) & (A.z > 0.f) & (A.w > 0.f) &
                          (B.x > 0.f) & (B.y > 0.f) & (B.z > 0.f) & (B.w > 0.f);
        } while (!ok);
        const float S = ((fabsf(A.x) + fabsf(A.y)) + (fabsf(A.z) + fabsf(A.w)))
                      + ((fabsf(B.x) + fabsf(B.y)) + (fabsf(B.z) + fabsf(B.w)));

        // --- epilogue
        const float rinv = rcp(S);
        const int   row  = r & (Nn - 1);
        #pragma unroll
        for (int k = 0; k < K; k++) {
            const float y = e[k] * rinv;
            out[(size_t)row * Mm + col0 + k * TPB] = o_acc[k] + y;
            c[k]     = __fmaf_rn(-y, c[k], c[k]);
            a2[k]    = a2n[k];
            o_acc[k] = o_nx[k];
        }
    }
}

extern "C" void kernel_launch(void* const* d_in, const int* in_sizes, int n_in,
                              void* d_out, int out_size) {
    const float* V = (const float*)d_in[0];
    float* out = (float*)d_out;
    (void)in_sizes; (void)n_in; (void)out_size;

    softrr_init<<<Nn, 256>>>(V);
    softrr_main<<<C, TPB>>>(V, out);
}